// round 15
// baseline (speedup 1.0000x reference)
#include <cuda_runtime.h>
#include <cstdint>
#include <cstddef>

#define T_DIM 2048
#define B_DIM 32
#define E_DIM 512
#define N_DIM 512
#define K_DIM 512
#define M_DIM (T_DIM * B_DIM)   // 65536 rows, row m = t*B + b

// ---------------- device scratch ----------------
__device__ float g_w[M_DIM];
__device__ int   g_len[B_DIM];
__device__ int   g_nrows[B_DIM];
__device__ int   g_rt0[B_DIM * T_DIM];
__device__ int   g_rt1[B_DIM * T_DIM];
__device__ float g_rc0[B_DIM * T_DIM];
__device__ float g_rc1[B_DIM * T_DIM];
__device__ float g_rmult[B_DIM * T_DIM];
// fused-scan state (re-zeroed by k0 every launch)
__device__ float    g_sprev[B_DIM];
__device__ float    g_squant[B_DIM];
__device__ int      g_scanpos[B_DIM];
__device__ int      g_slock[B_DIM];
__device__ unsigned g_sdone[B_DIM];
__device__ float    g_prevA[M_DIM];        // [b][t] = b*T_DIM + t
__device__ unsigned g_fireM[B_DIM * 64];

// ---------------- f32x2 helpers ----------------
typedef unsigned long long u64;
__device__ __forceinline__ u64 fma2(u64 a, u64 b, u64 c) {
    u64 d;
    asm("fma.rn.f32x2 %0, %1, %2, %3;" : "=l"(d) : "l"(a), "l"(b), "l"(c));
    return d;
}
__device__ __forceinline__ u64 dupf(float a) {
    u64 d;
    asm("mov.b64 %0, {%1, %1};" : "=l"(d) : "f"(a));
    return d;
}
__device__ __forceinline__ void unpk(u64 v, float& lo, float& hi) {
    asm("mov.b64 {%0, %1}, %2;" : "=f"(lo), "=f"(hi) : "l"(v));
}

// ---------------- K0: mask detect + lengths + state reset -------------------
__global__ void k0_mask(const void* __restrict__ mask) {
    __shared__ int flags[3];
    int tid = threadIdx.x;
    if (tid < 3) flags[tid] = 0;
    // reset fused-scan state (every graph replay)
    if (tid < B_DIM) {
        g_sprev[tid] = 0.f; g_squant[tid] = 0.f;
        g_scanpos[tid] = 0; g_slock[tid] = 0; g_sdone[tid] = 0u;
    }
    for (int i = tid; i < B_DIM * 64; i += 1024) g_fireM[i] = 0u;
    __syncthreads();
    const unsigned* dw = (const unsigned*)mask;
    for (int i = tid; i < 16384; i += blockDim.x) {
        unsigned d = dw[i];
        if (d != 0u) {
            if (d == 1u)                flags[0] = 1;
            else if (d == 0x3F800000u)  flags[1] = 1;
            else                        flags[2] = 1;
        }
    }
    __syncthreads();
    int kind = flags[2] ? 2 : (flags[1] ? 1 : 0);
    int warp = tid >> 5, lane = tid & 31;
    int cnt = 0;
    if (kind == 2) {
        const unsigned char* p = (const unsigned char*)mask + warp * T_DIM;
        for (int t = lane; t < T_DIM; t += 32) cnt += (p[t] == 0);
    } else {
        const unsigned* p = dw + (size_t)warp * T_DIM;
        for (int t = lane; t < T_DIM; t += 32) cnt += (p[t] == 0u);
    }
    for (int o = 16; o > 0; o >>= 1) cnt += __shfl_down_sync(0xffffffffu, cnt, o);
    if (lane == 0) g_len[warp] = cnt;
}

// ---------------- K_zero: zero-fill outputs (concurrent with k1) ------------
__global__ __launch_bounds__(256) void k_zero(float* __restrict__ out_cif,
                                              float* __restrict__ out_mask,
                                              float* __restrict__ out_marks,
                                              int extras)
{
    const size_t stride = (size_t)gridDim.x * blockDim.x;
    const size_t i0 = (size_t)blockIdx.x * blockDim.x + threadIdx.x;
    const float4 z = make_float4(0.f, 0.f, 0.f, 0.f);
    float4* p = (float4*)out_cif;
    const size_t n4 = (size_t)M_DIM * E_DIM / 4;
    for (size_t j = i0; j < n4; j += stride) p[j] = z;
    if (extras) {
        float4* pm = (float4*)out_mask;
        float4* pk = (float4*)out_marks;
        for (size_t j = i0; j < M_DIM / 4; j += stride) { pm[j] = z; pk[j] = z; }
    }
}

// ---------------- K1: fused fp32 GEMM + incremental CIF scan ----------------
#define BMT 128
#define BNT 128
#define BKT 16
#define KTILES (K_DIM / BKT)   // 32
#define AS_STR (BMT + 4)

__global__ __launch_bounds__(256, 2) void k1_gemm(
    const float* __restrict__ A,   // [T][B][E]; row(t,b) at ((t*B)+b)*E
    const float* __restrict__ W1,  // [K][N] row-major
    const float* __restrict__ b1,  // [N]
    const float* __restrict__ w2,  // [N]
    const float* __restrict__ b2)  // [1]
{
    const int b = blockIdx.y;
    const int t0 = blockIdx.x * BMT;
    const int L = g_len[b];
    if (t0 >= L) return;          // whole tile is padding: weights never read

    __shared__ float As[2][BKT][AS_STR];
    __shared__ __align__(16) float Bs[2][BKT][BNT];
    __shared__ float red[BMT][17];

    const int tid = threadIdx.x;
    const int tx = tid & 15, ty = tid >> 4;

    const int aRow0 = tid >> 2;
    const int aRow1 = aRow0 + 64;
    const int aCol  = (tid & 3) * 4;
    const int bRow0 = tid >> 5;
    const int bRow1 = bRow0 + 8;
    const int bCol  = (tid & 31) * 4;

    const float* aP0 = A + ((size_t)(t0 + aRow0) * B_DIM + b) * K_DIM + aCol;
    const float* aP1 = A + ((size_t)(t0 + aRow1) * B_DIM + b) * K_DIM + aCol;

    float rowacc[8];
#pragma unroll
    for (int i = 0; i < 8; i++) rowacc[i] = 0.f;
    const float b2s = b2[0];

    for (int n0 = 0; n0 < N_DIM; n0 += BNT) {
        u64 acc2[8][4];
#pragma unroll
        for (int i = 0; i < 8; i++)
#pragma unroll
            for (int j = 0; j < 4; j++) acc2[i][j] = 0ull;

        float4 aR0, aR1, bR0, bR1;
        aR0 = *(const float4*)(aP0);
        aR1 = *(const float4*)(aP1);
        bR0 = *(const float4*)(W1 + (size_t)bRow0 * N_DIM + n0 + bCol);
        bR1 = *(const float4*)(W1 + (size_t)bRow1 * N_DIM + n0 + bCol);
        As[0][aCol + 0][aRow0] = aR0.x; As[0][aCol + 1][aRow0] = aR0.y;
        As[0][aCol + 2][aRow0] = aR0.z; As[0][aCol + 3][aRow0] = aR0.w;
        As[0][aCol + 0][aRow1] = aR1.x; As[0][aCol + 1][aRow1] = aR1.y;
        As[0][aCol + 2][aRow1] = aR1.z; As[0][aCol + 3][aRow1] = aR1.w;
        *(float4*)&Bs[0][bRow0][bCol] = bR0;
        *(float4*)&Bs[0][bRow1][bCol] = bR1;
        __syncthreads();

        for (int kt = 0; kt < KTILES; kt++) {
            const int cur = kt & 1;
            if (kt + 1 < KTILES) {
                const int kb = (kt + 1) * BKT;
                aR0 = *(const float4*)(aP0 + kb);
                aR1 = *(const float4*)(aP1 + kb);
                bR0 = *(const float4*)(W1 + (size_t)(kb + bRow0) * N_DIM + n0 + bCol);
                bR1 = *(const float4*)(W1 + (size_t)(kb + bRow1) * N_DIM + n0 + bCol);
            }
#pragma unroll
            for (int kk = 0; kk < BKT; kk++) {
                float4 a0 = *(const float4*)&As[cur][kk][ty * 8];
                float4 a1 = *(const float4*)&As[cur][kk][ty * 8 + 4];
                const u64* bp = (const u64*)&Bs[cur][kk][tx * 8];
                u64 b0 = bp[0], b1v = bp[1], b2v = bp[2], b3 = bp[3];
                float av[8] = {a0.x, a0.y, a0.z, a0.w, a1.x, a1.y, a1.z, a1.w};
#pragma unroll
                for (int i = 0; i < 8; i++) {
                    u64 ad = dupf(av[i]);
                    acc2[i][0] = fma2(ad, b0,  acc2[i][0]);
                    acc2[i][1] = fma2(ad, b1v, acc2[i][1]);
                    acc2[i][2] = fma2(ad, b2v, acc2[i][2]);
                    acc2[i][3] = fma2(ad, b3,  acc2[i][3]);
                }
            }
            if (kt + 1 < KTILES) {
                const int nb = cur ^ 1;
                As[nb][aCol + 0][aRow0] = aR0.x; As[nb][aCol + 1][aRow0] = aR0.y;
                As[nb][aCol + 2][aRow0] = aR0.z; As[nb][aCol + 3][aRow0] = aR0.w;
                As[nb][aCol + 0][aRow1] = aR1.x; As[nb][aCol + 1][aRow1] = aR1.y;
                As[nb][aCol + 2][aRow1] = aR1.z; As[nb][aCol + 3][aRow1] = aR1.w;
                *(float4*)&Bs[nb][bRow0][bCol] = bR0;
                *(float4*)&Bs[nb][bRow1][bCol] = bR1;
                __syncthreads();
            }
        }

        float b1r[8], w2r[8];
#pragma unroll
        for (int j = 0; j < 8; j++) {
            b1r[j] = b1[n0 + tx * 8 + j];
            w2r[j] = w2[n0 + tx * 8 + j];
        }
#pragma unroll
        for (int i = 0; i < 8; i++)
#pragma unroll
            for (int j2 = 0; j2 < 4; j2++) {
                float clo, chi;
                unpk(acc2[i][j2], clo, chi);
                float h0 = fmaxf(clo + b1r[j2 * 2], 0.f);
                float h1 = fmaxf(chi + b1r[j2 * 2 + 1], 0.f);
                rowacc[i] = fmaf(h0, w2r[j2 * 2], rowacc[i]);
                rowacc[i] = fmaf(h1, w2r[j2 * 2 + 1], rowacc[i]);
            }
        __syncthreads();
    }

#pragma unroll
    for (int i = 0; i < 8; i++) red[ty * 8 + i][tx] = rowacc[i];
    __syncthreads();
    if (tid < BMT) {
        float s = 0.f;
#pragma unroll
        for (int x = 0; x < 16; x++) s += red[tid][x];
        float arg = s + b2s;
        g_w[(size_t)(t0 + tid) * B_DIM + b] = 1.0f / (1.0f + expf(-arg));
    }
    __syncthreads();

    // -------- incremental scan: publish tile, then scan forward if possible
    if (tid == 0) {
        __threadfence();
        atomicOr(&g_sdone[b], 1u << blockIdx.x);
        const int ntiles = (L + BMT - 1) / BMT;
        const int base = b * T_DIM;
        for (;;) {
            int pos = atomicAdd(&g_scanpos[b], 0);
            if (pos >= ntiles) break;
            unsigned done = atomicOr(&g_sdone[b], 0u);
            if (!((done >> pos) & 1u)) break;
            if (atomicCAS(&g_slock[b], 0, 1) != 0) break;
            __threadfence();
            pos = atomicAdd(&g_scanpos[b], 0);
            done = atomicOr(&g_sdone[b], 0u);
            float prev = __ldcg(&g_sprev[b]);
            float q    = __ldcg(&g_squant[b]);
            while (pos < ntiles && ((done >> pos) & 1u)) {
                const int tbeg = pos * BMT;
                const int tend = (tbeg + BMT < L) ? (tbeg + BMT) : L;
                unsigned mb = 0u;
#pragma unroll 4
                for (int t = tbeg; t < tend; t++) {
                    float w = __ldcg(&g_w[(size_t)t * B_DIM + b]);
                    float remained = 1.0f - prev;
                    float sum = prev + w;
                    float alt = w - remained;
                    bool fired = (sum >= 1.0f);
                    prev = fired ? alt : sum;
                    q += w;
                    g_prevA[base + t] = prev;
                    mb |= (fired ? 1u : 0u) << (t & 31);
                    if ((t & 31) == 31) { g_fireM[b * 64 + (t >> 5)] = mb; mb = 0u; }
                }
                if (tend & 31) g_fireM[b * 64 + ((tend - 1) >> 5)] = mb;
                pos++;
                done = atomicOr(&g_sdone[b], 0u);
            }
            __stcg(&g_sprev[b], prev);
            __stcg(&g_squant[b], q);
            __threadfence();
            atomicExch(&g_scanpos[b], pos);
            atomicExch(&g_slock[b], 0);
            // loop: re-check in case tiles completed while we held the lock
        }
    }
}

// ---------------- K2_emit: records/marks/quantity from scan scratch ---------
__global__ __launch_bounds__(256) void k2_emit(float* __restrict__ out_marks,
                                               float* __restrict__ out_quantity,
                                               int write_extras)
{
    __shared__ unsigned fireM[64];
    __shared__ int wpre[65];
    __shared__ int fireIdx[T_DIM];

    const int b = blockIdx.x;
    const int tid = threadIdx.x;
    const int L = g_len[b];
    const int base = b * T_DIM;

    if (tid < 64) fireM[tid] = g_fireM[b * 64 + tid];
    __syncthreads();
    if (tid == 0) {
        int acc = 0;
        for (int i = 0; i < 64; i++) { wpre[i] = acc; acc += __popc(fireM[i]); }
        wpre[64] = acc;
    }
    __syncthreads();
    if (tid < 64) {
        unsigned bits = fireM[tid];
        int o = wpre[tid];
        while (bits) {
            int bb = __ffs(bits) - 1;
            fireIdx[o++] = tid * 32 + bb;
            bits &= bits - 1;
        }
    }
    __syncthreads();

    const int Rf = wpre[64];
    const float w0 = g_w[b];   // t = 0
    for (int r = tid; r < Rf; r += 256) {
        int t1 = fireIdx[r];
        int t0 = (r == 0) ? 0 : fireIdx[r - 1];
        float c0 = (r == 0) ? w0 : g_prevA[base + t0];
        float c1 = (t1 > 0) ? (1.0f - g_prevA[base + t1 - 1]) : 1.0f;
        int idx = base + r;
        g_rt0[idx] = t0; g_rt1[idx] = t1;
        g_rc0[idx] = c0; g_rc1[idx] = c1;
        g_rmult[idx] = 1.0f;
        if (write_extras) out_marks[base + t1] = 1.f;
    }
    if (tid == 0) {
        int r = Rf;
        float prevL = g_prevA[base + L - 1];   // L >= 1
        if (L < T_DIM && prevL > 0.6f) {
            int t0 = Rf ? fireIdx[Rf - 1] : 0;
            float c0 = Rf ? g_prevA[base + t0] : w0;
            int idx = base + r;
            g_rt0[idx] = t0; g_rt1[idx] = L - 1;
            g_rc0[idx] = c0; g_rc1[idx] = g_w[(size_t)(L - 1) * B_DIM + b];
            g_rmult[idx] = 1.0f / (prevL + 1e-10f);
            if (write_extras) out_marks[base + L] = 1.f;
            r++;
        }
        g_nrows[b] = r;
        if (write_extras) out_quantity[b] = g_squant[b];
    }
}

// ---------------- K3: segment sums, fired rows only (zeros pre-filled) ------
__global__ __launch_bounds__(128) void k3_rows(
    const float* __restrict__ x,
    float* __restrict__ out_cif,
    float* __restrict__ out_mask,
    int write_extras)
{
    const int r = blockIdx.x, b = blockIdx.y;
    const int tid = threadIdx.x;
    if (r >= g_nrows[b]) return;

    const int idx = b * T_DIM + r;
    const int t0 = g_rt0[idx], t1 = g_rt1[idx];
    const float c0 = g_rc0[idx], c1 = g_rc1[idx], mult = g_rmult[idx];
    const float* xb = x + (size_t)b * E_DIM + tid * 4;
    const size_t tstride = (size_t)B_DIM * E_DIM;

    float4 acc;
    float4 v = *(const float4*)(xb + (size_t)t0 * tstride);
    acc.x = c0 * v.x; acc.y = c0 * v.y; acc.z = c0 * v.z; acc.w = c0 * v.w;
    for (int t = t0 + 1; t < t1; t++) {
        float w = g_w[t * B_DIM + b];
        v = *(const float4*)(xb + (size_t)t * tstride);
        acc.x = fmaf(w, v.x, acc.x); acc.y = fmaf(w, v.y, acc.y);
        acc.z = fmaf(w, v.z, acc.z); acc.w = fmaf(w, v.w, acc.w);
    }
    if (t1 > t0) {
        v = *(const float4*)(xb + (size_t)t1 * tstride);
        acc.x = fmaf(c1, v.x, acc.x); acc.y = fmaf(c1, v.y, acc.y);
        acc.z = fmaf(c1, v.z, acc.z); acc.w = fmaf(c1, v.w, acc.w);
    }
    acc.x *= mult; acc.y *= mult; acc.z *= mult; acc.w *= mult;
    *(float4*)(out_cif + ((size_t)(b * T_DIM + r)) * E_DIM + tid * 4) = acc;
    if (write_extras && tid == 0) out_mask[b * T_DIM + r] = 1.f;
}

// ---------------- launch ----------------------------------------------------
extern "C" void kernel_launch(void* const* d_in, const int* in_sizes, int n_in,
                              void* d_out, int out_size)
{
    const float* enc = (const float*)d_in[0];
    const void*  mask = d_in[1];
    const float* dense_w = (const float*)d_in[2];
    const float* dense_b = (const float*)d_in[3];
    const float* wproj_w = (const float*)d_in[4];
    const float* wproj_b = (const float*)d_in[5];
    float* out = (float*)d_out;

    const int cif_elems = B_DIM * T_DIM * E_DIM;
    const int full = cif_elems + B_DIM * T_DIM + B_DIM + B_DIM * T_DIM;
    const int extras = (out_size >= full) ? 1 : 0;

    float* out_mask   = out + cif_elems;
    float* out_q      = out_mask + B_DIM * T_DIM;
    float* out_marks  = out_q + B_DIM;

    // side stream for the zero-fill, forked/joined via events (graph-capturable)
    cudaStream_t s;
    cudaStreamCreateWithFlags(&s, cudaStreamNonBlocking);
    cudaEvent_t evF, evJ;
    cudaEventCreateWithFlags(&evF, cudaEventDisableTiming);
    cudaEventCreateWithFlags(&evJ, cudaEventDisableTiming);

    cudaEventRecord(evF, 0);
    cudaStreamWaitEvent(s, evF, 0);
    k_zero<<<1024, 256, 0, s>>>(out, out_mask, out_marks, extras);
    cudaEventRecord(evJ, s);

    k0_mask<<<1, 1024>>>(mask);
    k1_gemm<<<dim3(T_DIM / BMT, B_DIM), 256>>>(enc, dense_w, dense_b, wproj_w, wproj_b);
    cudaStreamWaitEvent(0, evJ, 0);   // zero-fill done before marks/cif writes
    k2_emit<<<B_DIM, 256>>>(out_marks, out_q, extras);
    k3_rows<<<dim3(T_DIM, B_DIM), 128>>>(enc, out, out_mask, extras);
}

// round 17
// speedup vs baseline: 1.4714x; 1.4714x over previous
#include <cuda_runtime.h>
#include <cstdint>
#include <cstddef>

#define T_DIM 2048
#define B_DIM 32
#define E_DIM 512
#define N_DIM 512
#define K_DIM 512
#define M_DIM (T_DIM * B_DIM)   // 65536 rows, row m = t*B + b

// ---------------- device scratch ----------------
__device__ float g_w[M_DIM];
__device__ int   g_len[B_DIM];
__device__ int   g_nrows[B_DIM];
__device__ int   g_rt0[B_DIM * T_DIM];
__device__ int   g_rt1[B_DIM * T_DIM];
__device__ float g_rc0[B_DIM * T_DIM];
__device__ float g_rc1[B_DIM * T_DIM];
__device__ float g_rmult[B_DIM * T_DIM];
__device__ int   g_markpos[B_DIM * T_DIM];
__device__ float g_squant[B_DIM];
__device__ unsigned g_sdone[B_DIM];      // per-batch tile-completion bits
__device__ float    g_prevA[M_DIM];      // [b][t] = b*T_DIM + t
__device__ unsigned g_fireM[B_DIM * 64];
__device__ int      g_fireIdx[B_DIM * T_DIM];

// ---------------- f32x2 helpers ----------------
typedef unsigned long long u64;
__device__ __forceinline__ u64 fma2(u64 a, u64 b, u64 c) {
    u64 d;
    asm("fma.rn.f32x2 %0, %1, %2, %3;" : "=l"(d) : "l"(a), "l"(b), "l"(c));
    return d;
}
__device__ __forceinline__ u64 dupf(float a) {
    u64 d;
    asm("mov.b64 %0, {%1, %1};" : "=l"(d) : "f"(a));
    return d;
}
__device__ __forceinline__ void unpk(u64 v, float& lo, float& hi) {
    asm("mov.b64 {%0, %1}, %2;" : "=f"(lo), "=f"(hi) : "l"(v));
}

// ---------------- K0: mask detect + lengths + state reset -------------------
__global__ void k0_mask(const void* __restrict__ mask) {
    __shared__ int flags[3];
    int tid = threadIdx.x;
    if (tid < 3) flags[tid] = 0;
    if (tid < B_DIM) g_sdone[tid] = 0u;
    __syncthreads();
    const unsigned* dw = (const unsigned*)mask;
    for (int i = tid; i < 16384; i += blockDim.x) {
        unsigned d = dw[i];
        if (d != 0u) {
            if (d == 1u)                flags[0] = 1;
            else if (d == 0x3F800000u)  flags[1] = 1;
            else                        flags[2] = 1;
        }
    }
    __syncthreads();
    int kind = flags[2] ? 2 : (flags[1] ? 1 : 0);
    int warp = tid >> 5, lane = tid & 31;
    int cnt = 0;
    if (kind == 2) {
        const unsigned char* p = (const unsigned char*)mask + warp * T_DIM;
        for (int t = lane; t < T_DIM; t += 32) cnt += (p[t] == 0);
    } else {
        const unsigned* p = dw + (size_t)warp * T_DIM;
        for (int t = lane; t < T_DIM; t += 32) cnt += (p[t] == 0u);
    }
    for (int o = 16; o > 0; o >>= 1) cnt += __shfl_down_sync(0xffffffffu, cnt, o);
    if (lane == 0) g_len[warp] = cnt;
}

// ---------------- K_zero: zero-fill outputs (concurrent with k1) ------------
__global__ __launch_bounds__(256) void k_zero(float* __restrict__ out_cif,
                                              float* __restrict__ out_mask,
                                              float* __restrict__ out_marks,
                                              int extras)
{
    const size_t stride = (size_t)gridDim.x * blockDim.x;
    const size_t i0 = (size_t)blockIdx.x * blockDim.x + threadIdx.x;
    const float4 z = make_float4(0.f, 0.f, 0.f, 0.f);
    float4* p = (float4*)out_cif;
    const size_t n4 = (size_t)M_DIM * E_DIM / 4;
    for (size_t j = i0; j < n4; j += stride) p[j] = z;
    if (extras) {
        float4* pm = (float4*)out_mask;
        float4* pk = (float4*)out_marks;
        for (size_t j = i0; j < M_DIM / 4; j += stride) { pm[j] = z; pk[j] = z; }
    }
}

// ---------------- scan worker: one warp handles one batch -------------------
#define BMT 128
__device__ __noinline__ void scan_batch_warp(int b, float* ws) {
    const int lane = threadIdx.x & 31;
    const int L = g_len[b];
    const int base = b * T_DIM;
    const int ntiles = (L + BMT - 1) / BMT;

    float prev = 0.f, q = 0.f;
    unsigned mbits = 0u;
    for (int pos = 0; pos < ntiles; pos++) {
        if (lane == 0) {
            while (!((atomicOr(&g_sdone[b], 0u) >> pos) & 1u)) __nanosleep(128);
        }
        __syncwarp();
        const int tbeg = pos * BMT;
#pragma unroll
        for (int k = 0; k < 4; k++) {
            const int t = tbeg + lane + 32 * k;
            if (t < L) ws[lane + 32 * k] = __ldcg(&g_w[(size_t)t * B_DIM + b]);
        }
        __syncwarp();
        if (lane == 0) {
            const int cnt = (tbeg + BMT < L) ? BMT : (L - tbeg);
            const int c8 = cnt & ~7;
            int j = 0;
            for (; j < c8; j += 8) {
                float4 wa = *(const float4*)&ws[j];
                float4 wb = *(const float4*)&ws[j + 4];
                float wv[8] = {wa.x, wa.y, wa.z, wa.w, wb.x, wb.y, wb.z, wb.w};
#pragma unroll
                for (int e = 0; e < 8; e++) {
                    const int t = tbeg + j + e;
                    float w = wv[e];
                    float remained = 1.0f - prev;
                    float sum = prev + w;
                    float alt = w - remained;
                    bool fired = (sum >= 1.0f);
                    prev = fired ? alt : sum;
                    q += w;
                    g_prevA[base + t] = prev;
                    mbits |= (fired ? 1u : 0u) << (t & 31);
                    if ((t & 31) == 31) { g_fireM[b * 64 + (t >> 5)] = mbits; mbits = 0u; }
                }
            }
            for (; j < cnt; j++) {
                const int t = tbeg + j;
                float w = ws[j];
                float remained = 1.0f - prev;
                float sum = prev + w;
                float alt = w - remained;
                bool fired = (sum >= 1.0f);
                prev = fired ? alt : sum;
                q += w;
                g_prevA[base + t] = prev;
                mbits |= (fired ? 1u : 0u) << (t & 31);
                if ((t & 31) == 31) { g_fireM[b * 64 + (t >> 5)] = mbits; mbits = 0u; }
            }
        }
        __syncwarp();
    }
    if (lane == 0 && (L & 31)) g_fireM[b * 64 + ((L - 1) >> 5)] = mbits;
    __syncwarp();
    __threadfence_block();

    // prefix + expand fire indices (warp-parallel)
    unsigned wd0 = g_fireM[b * 64 + lane];
    unsigned wd1 = g_fireM[b * 64 + 32 + lane];
    int c0 = __popc(wd0), c1 = __popc(wd1);
    int i0 = c0, i1 = c1;
    for (int o = 1; o < 32; o <<= 1) {
        int y0 = __shfl_up_sync(0xffffffffu, i0, o);
        int y1 = __shfl_up_sync(0xffffffffu, i1, o);
        if (lane >= o) { i0 += y0; i1 += y1; }
    }
    const int tot0 = __shfl_sync(0xffffffffu, i0, 31);
    const int tot1 = __shfl_sync(0xffffffffu, i1, 31);
    int o0 = i0 - c0;
    int o1 = tot0 + i1 - c1;
    unsigned bits = wd0;
    while (bits) {
        int bb = __ffs(bits) - 1;
        g_fireIdx[base + o0++] = lane * 32 + bb;
        bits &= bits - 1;
    }
    bits = wd1;
    while (bits) {
        int bb = __ffs(bits) - 1;
        g_fireIdx[base + o1++] = (32 + lane) * 32 + bb;
        bits &= bits - 1;
    }
    const int Rf = tot0 + tot1;
    __syncwarp();
    __threadfence_block();

    const float w0v = __ldcg(&g_w[b]);   // t = 0
    for (int r = lane; r < Rf; r += 32) {
        int t1 = g_fireIdx[base + r];
        int t0 = (r == 0) ? 0 : g_fireIdx[base + r - 1];
        float c0v = (r == 0) ? w0v : g_prevA[base + t0];
        float c1v = (t1 > 0) ? (1.0f - g_prevA[base + t1 - 1]) : 1.0f;
        int idx = base + r;
        g_rt0[idx] = t0; g_rt1[idx] = t1;
        g_rc0[idx] = c0v; g_rc1[idx] = c1v;
        g_rmult[idx] = 1.0f;
        g_markpos[idx] = t1;
    }
    if (lane == 0) {
        int r = Rf;
        float prevL = g_prevA[base + L - 1];   // L >= 1
        if (L < T_DIM && prevL > 0.6f) {
            int t0 = Rf ? g_fireIdx[base + Rf - 1] : 0;
            float c0v = Rf ? g_prevA[base + t0] : w0v;
            int idx = base + r;
            g_rt0[idx] = t0; g_rt1[idx] = L - 1;
            g_rc0[idx] = c0v;
            g_rc1[idx] = __ldcg(&g_w[(size_t)(L - 1) * B_DIM + b]);
            g_rmult[idx] = 1.0f / (prevL + 1e-10f);
            g_markpos[idx] = L;
            r++;
        }
        g_nrows[b] = r;
        g_squant[b] = q;
    }
}

// ---------------- K1: fused fp32 GEMM + embedded scan blocks ----------------
#define BNT 128
#define BKT 16
#define KTILES (K_DIM / BKT)   // 32
#define AS_STR (BMT + 4)

__global__ __launch_bounds__(256, 2) void k1_gemm(
    const float* __restrict__ A,   // [T][B][E]; row(t,b) at ((t*B)+b)*E
    const float* __restrict__ W1,  // [K][N] row-major
    const float* __restrict__ b1,  // [N]
    const float* __restrict__ w2,  // [N]
    const float* __restrict__ b2)  // [1]
{
    __shared__ float As[2][BKT][AS_STR];
    __shared__ __align__(16) float Bs[2][BKT][BNT];
    __shared__ float red[BMT][17];

    if (blockIdx.x == 16) {        // scan blocks: y<4, one warp per batch
        if (blockIdx.y < 4) {
            const int warp = threadIdx.x >> 5;
            const int b = blockIdx.y * 8 + warp;
            float* ws = &As[0][0][0] + warp * AS_STR;   // 128 floats per warp
            scan_batch_warp(b, ws);
        }
        return;
    }

    const int b = blockIdx.y;
    const int t0 = blockIdx.x * BMT;
    if (t0 >= g_len[b]) return;   // whole tile is padding: weights never read

    const int tid = threadIdx.x;
    const int tx = tid & 15, ty = tid >> 4;

    const int aRow0 = tid >> 2;
    const int aRow1 = aRow0 + 64;
    const int aCol  = (tid & 3) * 4;
    const int bRow0 = tid >> 5;
    const int bRow1 = bRow0 + 8;
    const int bCol  = (tid & 31) * 4;

    const float* aP0 = A + ((size_t)(t0 + aRow0) * B_DIM + b) * K_DIM + aCol;
    const float* aP1 = A + ((size_t)(t0 + aRow1) * B_DIM + b) * K_DIM + aCol;

    float rowacc[8];
#pragma unroll
    for (int i = 0; i < 8; i++) rowacc[i] = 0.f;
    const float b2s = b2[0];

    for (int n0 = 0; n0 < N_DIM; n0 += BNT) {
        u64 acc2[8][4];
#pragma unroll
        for (int i = 0; i < 8; i++)
#pragma unroll
            for (int j = 0; j < 4; j++) acc2[i][j] = 0ull;

        float4 aR0, aR1, bR0, bR1;
        aR0 = *(const float4*)(aP0);
        aR1 = *(const float4*)(aP1);
        bR0 = *(const float4*)(W1 + (size_t)bRow0 * N_DIM + n0 + bCol);
        bR1 = *(const float4*)(W1 + (size_t)bRow1 * N_DIM + n0 + bCol);
        As[0][aCol + 0][aRow0] = aR0.x; As[0][aCol + 1][aRow0] = aR0.y;
        As[0][aCol + 2][aRow0] = aR0.z; As[0][aCol + 3][aRow0] = aR0.w;
        As[0][aCol + 0][aRow1] = aR1.x; As[0][aCol + 1][aRow1] = aR1.y;
        As[0][aCol + 2][aRow1] = aR1.z; As[0][aCol + 3][aRow1] = aR1.w;
        *(float4*)&Bs[0][bRow0][bCol] = bR0;
        *(float4*)&Bs[0][bRow1][bCol] = bR1;
        __syncthreads();

        for (int kt = 0; kt < KTILES; kt++) {
            const int cur = kt & 1;
            if (kt + 1 < KTILES) {
                const int kb = (kt + 1) * BKT;
                aR0 = *(const float4*)(aP0 + kb);
                aR1 = *(const float4*)(aP1 + kb);
                bR0 = *(const float4*)(W1 + (size_t)(kb + bRow0) * N_DIM + n0 + bCol);
                bR1 = *(const float4*)(W1 + (size_t)(kb + bRow1) * N_DIM + n0 + bCol);
            }
#pragma unroll
            for (int kk = 0; kk < BKT; kk++) {
                float4 a0 = *(const float4*)&As[cur][kk][ty * 8];
                float4 a1 = *(const float4*)&As[cur][kk][ty * 8 + 4];
                const u64* bp = (const u64*)&Bs[cur][kk][tx * 8];
                u64 b0 = bp[0], b1v = bp[1], b2v = bp[2], b3 = bp[3];
                float av[8] = {a0.x, a0.y, a0.z, a0.w, a1.x, a1.y, a1.z, a1.w};
#pragma unroll
                for (int i = 0; i < 8; i++) {
                    u64 ad = dupf(av[i]);
                    acc2[i][0] = fma2(ad, b0,  acc2[i][0]);
                    acc2[i][1] = fma2(ad, b1v, acc2[i][1]);
                    acc2[i][2] = fma2(ad, b2v, acc2[i][2]);
                    acc2[i][3] = fma2(ad, b3,  acc2[i][3]);
                }
            }
            if (kt + 1 < KTILES) {
                const int nb = cur ^ 1;
                As[nb][aCol + 0][aRow0] = aR0.x; As[nb][aCol + 1][aRow0] = aR0.y;
                As[nb][aCol + 2][aRow0] = aR0.z; As[nb][aCol + 3][aRow0] = aR0.w;
                As[nb][aCol + 0][aRow1] = aR1.x; As[nb][aCol + 1][aRow1] = aR1.y;
                As[nb][aCol + 2][aRow1] = aR1.z; As[nb][aCol + 3][aRow1] = aR1.w;
                *(float4*)&Bs[nb][bRow0][bCol] = bR0;
                *(float4*)&Bs[nb][bRow1][bCol] = bR1;
                __syncthreads();
            }
        }

        float b1r[8], w2r[8];
#pragma unroll
        for (int j = 0; j < 8; j++) {
            b1r[j] = b1[n0 + tx * 8 + j];
            w2r[j] = w2[n0 + tx * 8 + j];
        }
#pragma unroll
        for (int i = 0; i < 8; i++)
#pragma unroll
            for (int j2 = 0; j2 < 4; j2++) {
                float clo, chi;
                unpk(acc2[i][j2], clo, chi);
                float h0 = fmaxf(clo + b1r[j2 * 2], 0.f);
                float h1 = fmaxf(chi + b1r[j2 * 2 + 1], 0.f);
                rowacc[i] = fmaf(h0, w2r[j2 * 2], rowacc[i]);
                rowacc[i] = fmaf(h1, w2r[j2 * 2 + 1], rowacc[i]);
            }
        __syncthreads();
    }

#pragma unroll
    for (int i = 0; i < 8; i++) red[ty * 8 + i][tx] = rowacc[i];
    __syncthreads();
    if (tid < BMT) {
        float s = 0.f;
#pragma unroll
        for (int x = 0; x < 16; x++) s += red[tid][x];
        float arg = s + b2s;
        g_w[(size_t)(t0 + tid) * B_DIM + b] = 1.0f / (1.0f + expf(-arg));
    }
    __syncthreads();
    if (tid == 0) {                 // publish this tile to the scan warps
        __threadfence();
        atomicOr(&g_sdone[b], 1u << blockIdx.x);
    }
}

// ---------------- K3: segment sums + marks/mask/quantity emission -----------
__global__ __launch_bounds__(128) void k3_rows(
    const float* __restrict__ x,
    float* __restrict__ out_cif,
    float* __restrict__ out_mask,
    float* __restrict__ out_marks,
    float* __restrict__ out_quantity,
    int write_extras)
{
    const int r = blockIdx.x, b = blockIdx.y;
    const int tid = threadIdx.x;
    if (r >= g_nrows[b]) return;

    const int idx = b * T_DIM + r;
    const int t0 = g_rt0[idx], t1 = g_rt1[idx];
    const float c0 = g_rc0[idx], c1 = g_rc1[idx], mult = g_rmult[idx];
    const float* xb = x + (size_t)b * E_DIM + tid * 4;
    const size_t tstride = (size_t)B_DIM * E_DIM;

    float4 acc;
    float4 v = *(const float4*)(xb + (size_t)t0 * tstride);
    acc.x = c0 * v.x; acc.y = c0 * v.y; acc.z = c0 * v.z; acc.w = c0 * v.w;
    for (int t = t0 + 1; t < t1; t++) {
        float w = g_w[t * B_DIM + b];
        v = *(const float4*)(xb + (size_t)t * tstride);
        acc.x = fmaf(w, v.x, acc.x); acc.y = fmaf(w, v.y, acc.y);
        acc.z = fmaf(w, v.z, acc.z); acc.w = fmaf(w, v.w, acc.w);
    }
    if (t1 > t0) {
        v = *(const float4*)(xb + (size_t)t1 * tstride);
        acc.x = fmaf(c1, v.x, acc.x); acc.y = fmaf(c1, v.y, acc.y);
        acc.z = fmaf(c1, v.z, acc.z); acc.w = fmaf(c1, v.w, acc.w);
    }
    acc.x *= mult; acc.y *= mult; acc.z *= mult; acc.w *= mult;
    *(float4*)(out_cif + ((size_t)(b * T_DIM + r)) * E_DIM + tid * 4) = acc;
    if (write_extras && tid == 0) {
        out_mask[b * T_DIM + r] = 1.f;
        out_marks[b * T_DIM + g_markpos[idx]] = 1.f;
        if (r == 0) out_quantity[b] = g_squant[b];
    }
}

// ---------------- launch ----------------------------------------------------
extern "C" void kernel_launch(void* const* d_in, const int* in_sizes, int n_in,
                              void* d_out, int out_size)
{
    const float* enc = (const float*)d_in[0];
    const void*  mask = d_in[1];
    const float* dense_w = (const float*)d_in[2];
    const float* dense_b = (const float*)d_in[3];
    const float* wproj_w = (const float*)d_in[4];
    const float* wproj_b = (const float*)d_in[5];
    float* out = (float*)d_out;

    const int cif_elems = B_DIM * T_DIM * E_DIM;
    const int full = cif_elems + B_DIM * T_DIM + B_DIM + B_DIM * T_DIM;
    const int extras = (out_size >= full) ? 1 : 0;

    float* out_mask   = out + cif_elems;
    float* out_q      = out_mask + B_DIM * T_DIM;
    float* out_marks  = out_q + B_DIM;

    // one side stream + two events, created ONCE (before the pre-capture
    // baseline, during the correctness call) -> no per-call allocations.
    static cudaStream_t sZ = 0;
    static cudaEvent_t evF = 0, evJ = 0;
    if (!sZ) {
        cudaStreamCreateWithFlags(&sZ, cudaStreamNonBlocking);
        cudaEventCreateWithFlags(&evF, cudaEventDisableTiming);
        cudaEventCreateWithFlags(&evJ, cudaEventDisableTiming);
    }

    cudaEventRecord(evF, 0);
    cudaStreamWaitEvent(sZ, evF, 0);
    k_zero<<<1024, 256, 0, sZ>>>(out, out_mask, out_marks, extras);
    cudaEventRecord(evJ, sZ);

    k0_mask<<<1, 1024>>>(mask);
    k1_gemm<<<dim3(17, B_DIM), 256>>>(enc, dense_w, dense_b, wproj_w, wproj_b);
    cudaStreamWaitEvent(0, evJ, 0);   // zero-fill done before output writes
    k3_rows<<<dim3(T_DIM, B_DIM), 128>>>(enc, out, out_mask, out_marks, out_q, extras);
}